// round 5
// baseline (speedup 1.0000x reference)
#include <cuda_runtime.h>

#define RESF  0.16f
#define XMINF -51.2f
#define YMINF -51.2f
#define EPSF  1e-5f
#define NEGF  -1000000000.0f

// Folded layer-1 weights (BN fused, 9-feature collapse -> 4 features + pillar bias)
__device__ float g_wx[64], g_wy[64], g_wz[64], g_wr[64];
__device__ float g_wxc[64], g_wyc[64], g_wzm[64], g_b1[64];
__device__ float g_b2[64];
// Layer-2 weights, BN-folded, packed per channel c as (W2[k][c], W2[k+32][c]) u64:
// g_w2p[c*32 + k], k = 0..31  (pairs with interleaved h1 layout, see below)
__device__ unsigned long long g_w2p[64 * 32];

// ---------------------------------------------------------------------------
// Prep kernel (thread j = output channel j)
// ---------------------------------------------------------------------------
__global__ void pfn_prep(const float* __restrict__ W1, const float* __restrict__ b1,
                         const float* __restrict__ g1, const float* __restrict__ beta1,
                         const float* __restrict__ m1, const float* __restrict__ v1,
                         const float* __restrict__ W2, const float* __restrict__ b2,
                         const float* __restrict__ g2, const float* __restrict__ beta2,
                         const float* __restrict__ m2, const float* __restrict__ v2) {
    int j = threadIdx.x;
    if (j >= 64) return;
    float a1 = g1[j] * rsqrtf(v1[j] + EPSF);
    float w4 = W1[4 * 64 + j], w5 = W1[5 * 64 + j], w6 = W1[6 * 64 + j];
    float w7 = W1[7 * 64 + j], w8 = W1[8 * 64 + j];
    g_wx[j]  = (W1[0 * 64 + j] + w4 + w7) * a1;
    g_wy[j]  = (W1[1 * 64 + j] + w5 + w8) * a1;
    g_wz[j]  = (W1[2 * 64 + j] + w6) * a1;
    g_wr[j]  = W1[3 * 64 + j] * a1;
    g_wxc[j] = (w4 + w7) * a1;
    g_wyc[j] = (w5 + w8) * a1;
    g_wzm[j] = w6 * a1;
    g_b1[j]  = (b1[j] - m1[j]) * a1 + beta1[j];

    float a2 = g2[j] * rsqrtf(v2[j] + EPSF);
    for (int k = 0; k < 32; k++) {
        float lo = W2[k * 64 + j] * a2;          // weight for h_k
        float hi = W2[(k + 32) * 64 + j] * a2;   // weight for h_{k+32}
        g_w2p[j * 32 + k] = ((unsigned long long)__float_as_uint(hi) << 32)
                          |  (unsigned long long)__float_as_uint(lo);
    }
    g_b2[j] = (b2[j] - m2[j]) * a2 + beta2[j];
}

// Packed f32x2 helpers (sm_100+; ptxas never auto-emits FFMA2)
#define FMA2(acc, a, b) \
    asm("fma.rn.f32x2 %0, %1, %2, %0;" : "+l"(acc) : "l"(a), "l"(b))
#define ADD2(d, a, b) \
    asm("add.rn.f32x2 %0, %1, %2;" : "=l"(d) : "l"(a), "l"(b))
#define UNPK2(lo, hi, v) \
    asm("mov.b64 {%0, %1}, %2;" : "=f"(lo), "=f"(hi) : "l"(v))

// ---------------------------------------------------------------------------
// Main kernel.
// CTA = 128 threads = 4 warps = 2 independent pillar streams.
// A stream = 2 warps (channel halves 0-31 / 32-63), synced by a NAMED barrier
// so the two streams in a CTA never couple (variable n => no barrier skew).
// Lane owns ONE channel c. h1 is stored INTERLEAVED: pos 2j <- h_j,
// pos 2j+1 <- h_{j+32}, so each LDS.128 delivers two (h_j, h_{j+32}) u64
// pairs that feed FFMA2 against pre-packed weight pairs (32 u64 regs/lane).
// Next pillar's points/coords/npts are prefetched during layer 2.
// coords/npts are int32 (JAX downgrades int64 without x64 mode).
// ---------------------------------------------------------------------------
__global__ __launch_bounds__(128, 4) void pfn_main(const float4* __restrict__ pillars,
                                                   const int* __restrict__ coords,
                                                   const int* __restrict__ npts,
                                                   float* __restrict__ out, int P) {
    __shared__ __align__(16) float  s_h1[2][32][64];   // per-stream, interleaved channels
    __shared__ __align__(16) float4 s_pts[2][32];      // per-stream raw points

    const int strm = threadIdx.x >> 6;        // pillar stream within CTA (0/1)
    const int half = (threadIdx.x >> 5) & 1;  // channel half (0: c<32, 1: c>=32)
    const int lane = threadIdx.x & 31;
    const int c    = half * 32 + lane;
    const int bar  = 1 + strm;                // named barrier id, 64 threads

    // Persistent weights: 32 packed u64 pairs for this lane's channel
    unsigned long long wq[32];
#pragma unroll
    for (int t = 0; t < 32; t++) wq[t] = g_w2p[c * 32 + t];

    const float wx = g_wx[c], wy = g_wy[c], wz = g_wz[c], wr = g_wr[c];
    const float wxc = g_wxc[c], wyc = g_wyc[c], wzm = g_wzm[c];
    const float b1c = g_b1[c], b2c = g_b2[c];

    const int stride = gridDim.x * 2;
    int p = blockIdx.x * 2 + strm;

    // Prime the pipeline: load first pillar's data
    float4 q = make_float4(0.f, 0.f, 0.f, 0.f);
    int n = 0, cx = 0, cy = 0;
    if (p < P) {
        q  = pillars[(long long)p * 32 + lane];
        n  = npts[p];  n = n < 0 ? 0 : (n > 32 ? 32 : n);
        cy = coords[2 * p];
        cx = coords[2 * p + 1];
    }

    while (p < P) {
        const int pn = p + stride;

        if (half == 0) s_pts[strm][lane] = q;

        const float xc = ((float)cx + 0.5f) * RESF + XMINF;
        const float yc = ((float)cy + 0.5f) * RESF + YMINF;

        // z-mean (warp shuffle reduce; both half-warps compute identically)
        float zv = (lane < n) ? q.z : 0.0f;
#pragma unroll
        for (int o = 16; o > 0; o >>= 1)
            zv += __shfl_xor_sync(0xffffffffu, zv, o);
        const float zm = zv / fmaxf((float)n, 1.0f);

        const float bias = b1c - xc * wxc - yc * wyc - zm * wzm;

        asm volatile("bar.sync %0, 64;" :: "r"(bar) : "memory");  // s_pts visible; prev L2 done

        // Layer 1: this lane's channel for every valid point, interleaved store
        for (int m = 0; m < n; m++) {
            float4 qm = s_pts[strm][m];
            float hv = fmaf(qm.x, wx, fmaf(qm.y, wy,
                       fmaf(qm.z, wz, fmaf(qm.w, wr, bias))));
            s_h1[strm][m][2 * lane + half] = fmaxf(hv, 0.0f);
        }

        // Prefetch next pillar (latency hidden under barrier + layer 2)
        float4 qn = make_float4(0.f, 0.f, 0.f, 0.f);
        int nn = 0, cxn = 0, cyn = 0;
        if (pn < P) {
            qn  = pillars[(long long)pn * 32 + lane];
            nn  = npts[pn];  nn = nn < 0 ? 0 : (nn > 32 ? 32 : nn);
            cyn = coords[2 * pn];
            cxn = coords[2 * pn + 1];
        }

        asm volatile("bar.sync %0, 64;" :: "r"(bar) : "memory");  // s_h1 visible

        // Layer 2 + running max: 16 LDS.128 + 32 FFMA2 per point
        float mx = NEGF;
        for (int m = 0; m < n; m++) {
            const ulonglong2* hp = (const ulonglong2*)s_h1[strm][m];
            unsigned long long a0 = 0ull, a1 = 0ull, a2 = 0ull, a3 = 0ull;
#pragma unroll
            for (int t = 0; t < 16; t++) {
                ulonglong2 hv2 = hp[t];   // (h_{2t},h_{2t+32}) | (h_{2t+1},h_{2t+33})
                if (t & 1) {
                    FMA2(a2, hv2.x, wq[2 * t]);
                    FMA2(a3, hv2.y, wq[2 * t + 1]);
                } else {
                    FMA2(a0, hv2.x, wq[2 * t]);
                    FMA2(a1, hv2.y, wq[2 * t + 1]);
                }
            }
            unsigned long long s01, s23, s;
            ADD2(s01, a0, a1);
            ADD2(s23, a2, a3);
            ADD2(s, s01, s23);
            float lo, hi;
            UNPK2(lo, hi, s);
            mx = fmaxf(mx, lo + hi);
        }

        out[(long long)p * 64 + c] = (n > 0) ? fmaxf(mx + b2c, 0.0f) : NEGF;

        q = qn; n = nn; cx = cxn; cy = cyn; p = pn;
    }
}

// ---------------------------------------------------------------------------
// kernel_launch
// Inputs: 0 pillars f32 (P,32,4)  1 coords i32 (P,2)  2 npts i32 (P,)
//         3 W1 4 b1 5 g1 6 beta1 7 m1 8 v1  9 W2 10 b2 11 g2 12 beta2 13 m2 14 v2
// Output: f32 (P, 64)
// ---------------------------------------------------------------------------
extern "C" void kernel_launch(void* const* d_in, const int* in_sizes, int n_in,
                              void* d_out, int out_size) {
    const float4* pillars = (const float4*)d_in[0];
    const int*    coords  = (const int*)d_in[1];
    const int*    npts    = (const int*)d_in[2];
    const int P = in_sizes[2];

    pfn_prep<<<1, 64>>>((const float*)d_in[3], (const float*)d_in[4],
                        (const float*)d_in[5], (const float*)d_in[6],
                        (const float*)d_in[7], (const float*)d_in[8],
                        (const float*)d_in[9], (const float*)d_in[10],
                        (const float*)d_in[11], (const float*)d_in[12],
                        (const float*)d_in[13], (const float*)d_in[14]);

    int grid = 2960;                        // 5920 pillar streams, ~17 pillars each
    if (grid * 2 > P) grid = (P + 1) / 2;
    pfn_main<<<grid, 128>>>(pillars, coords, npts, (float*)d_out, P);
}

// round 8
// speedup vs baseline: 1.5892x; 1.5892x over previous
#include <cuda_runtime.h>

#define RESF  0.16f
#define XMINF -51.2f
#define YMINF -51.2f
#define EPSF  1e-5f
#define NEGF  -1000000000.0f

// Folded layer-1 weights (BN fused, 9-feature collapse -> 4 features + pillar bias)
__device__ float g_wx[64], g_wy[64], g_wz[64], g_wr[64];
__device__ float g_wxc[64], g_wyc[64], g_wzm[64], g_b1[64];
__device__ float g_b2[64];
// Layer-2 weights, BN-folded, packed per channel as (w[2t][c], w[2t+1][c]) u64 pairs:
// g_w2p[c*32 + t]
__device__ unsigned long long g_w2p[64 * 32];

// ---------------------------------------------------------------------------
// Prep kernel (thread j = output channel j)
// ---------------------------------------------------------------------------
__global__ void pfn_prep(const float* __restrict__ W1, const float* __restrict__ b1,
                         const float* __restrict__ g1, const float* __restrict__ beta1,
                         const float* __restrict__ m1, const float* __restrict__ v1,
                         const float* __restrict__ W2, const float* __restrict__ b2,
                         const float* __restrict__ g2, const float* __restrict__ beta2,
                         const float* __restrict__ m2, const float* __restrict__ v2) {
    int j = threadIdx.x;
    if (j >= 64) return;
    float a1 = g1[j] * rsqrtf(v1[j] + EPSF);
    float w4 = W1[4 * 64 + j], w5 = W1[5 * 64 + j], w6 = W1[6 * 64 + j];
    float w7 = W1[7 * 64 + j], w8 = W1[8 * 64 + j];
    g_wx[j]  = (W1[0 * 64 + j] + w4 + w7) * a1;
    g_wy[j]  = (W1[1 * 64 + j] + w5 + w8) * a1;
    g_wz[j]  = (W1[2 * 64 + j] + w6) * a1;
    g_wr[j]  = W1[3 * 64 + j] * a1;
    g_wxc[j] = (w4 + w7) * a1;
    g_wyc[j] = (w5 + w8) * a1;
    g_wzm[j] = w6 * a1;
    g_b1[j]  = (b1[j] - m1[j]) * a1 + beta1[j];

    float a2 = g2[j] * rsqrtf(v2[j] + EPSF);
    for (int t = 0; t < 32; t++) {
        float lo = W2[(2 * t)     * 64 + j] * a2;
        float hi = W2[(2 * t + 1) * 64 + j] * a2;
        g_w2p[j * 32 + t] = ((unsigned long long)__float_as_uint(hi) << 32)
                          |  (unsigned long long)__float_as_uint(lo);
    }
    g_b2[j] = (b2[j] - m2[j]) * a2 + beta2[j];
}

// Packed f32x2 helpers (compiles on plain sm_103 target; ptxas never auto-emits FFMA2)
#define FMA2(acc, a, b) \
    asm("fma.rn.f32x2 %0, %1, %2, %0;" : "+l"(acc) : "l"(a), "l"(b))
#define ADD2(d, a, b) \
    asm("add.rn.f32x2 %0, %1, %2;" : "=l"(d) : "l"(a), "l"(b))
#define UNPK2(lo, hi, v) \
    asm("mov.b64 {%0, %1}, %2;" : "=f"(lo), "=f"(hi) : "l"(v))

// ---------------------------------------------------------------------------
// Main kernel: 1 warp = 1 pillar stream (warp-private smem, __syncwarp only).
// Lane owns channels (lane, lane+32); layer-2 weights = 64 packed u64 regs.
// Layer 2: 2 points per iteration (independent acc sets -> 2 LDS/FMA streams);
// per point: 16 broadcast LDS.128 + 64 FFMA2 (warp-wide).
// Next pillar's points/coords/npts prefetched during layer 2.
// coords/npts are int32 (JAX downgrades int64 without x64 mode).
// ---------------------------------------------------------------------------
__global__ __launch_bounds__(64, 6) void pfn_main(const float4* __restrict__ pillars,
                                                  const int2* __restrict__ coords,
                                                  const int* __restrict__ npts,
                                                  float* __restrict__ out, int P) {
    __shared__ __align__(16) float  s_h1[2][32][64];   // per-warp layer-1 activations
    __shared__ __align__(16) float4 s_pts[2][32];      // per-warp raw points

    const int w    = threadIdx.x >> 5;   // warp within CTA (pillar stream)
    const int lane = threadIdx.x & 31;
    const int cA   = lane;
    const int cB   = lane + 32;

    // Persistent per-lane weights: 32 packed u64 pairs per channel
    unsigned long long wA[32], wB[32];
#pragma unroll
    for (int t = 0; t < 32; t++) wA[t] = g_w2p[cA * 32 + t];
#pragma unroll
    for (int t = 0; t < 32; t++) wB[t] = g_w2p[cB * 32 + t];

    const float wxA = g_wx[cA], wyA = g_wy[cA], wzA = g_wz[cA], wrA = g_wr[cA];
    const float wxB = g_wx[cB], wyB = g_wy[cB], wzB = g_wz[cB], wrB = g_wr[cB];
    const float xcA = g_wxc[cA], ycA = g_wyc[cA], zmA = g_wzm[cA], b1A = g_b1[cA];
    const float xcB = g_wxc[cB], ycB = g_wyc[cB], zmB = g_wzm[cB], b1B = g_b1[cB];
    const float b2A = g_b2[cA], b2B = g_b2[cB];

    const int stride = gridDim.x * 2;
    int p = blockIdx.x * 2 + w;

    // Prime: first pillar's data
    float4 q = make_float4(0.f, 0.f, 0.f, 0.f);
    int n = 0; int2 cc = make_int2(0, 0);
    if (p < P) {
        q  = pillars[(long long)p * 32 + lane];
        n  = npts[p];  n = n < 0 ? 0 : (n > 32 ? 32 : n);
        cc = coords[p];
    }

    while (p < P) {
        const int pn = p + stride;

        __syncwarp();                     // prev layer-2 reads of s_h1 done
        s_pts[w][lane] = q;

        const float xc = ((float)cc.y + 0.5f) * RESF + XMINF;
        const float yc = ((float)cc.x + 0.5f) * RESF + YMINF;

        // z-mean over valid points (warp shuffle reduce)
        float zv = (lane < n) ? q.z : 0.0f;
#pragma unroll
        for (int o = 16; o > 0; o >>= 1)
            zv += __shfl_xor_sync(0xffffffffu, zv, o);
        const float zm = zv / fmaxf((float)n, 1.0f);

        const float biasA = b1A - xc * xcA - yc * ycA - zm * zmA;
        const float biasB = b1B - xc * xcB - yc * ycB - zm * zmB;

        __syncwarp();                     // s_pts visible

        // Layer 1: both channels for every valid point
        for (int m = 0; m < n; m++) {
            float4 qm = s_pts[w][m];
            float hA = fmaf(qm.x, wxA, fmaf(qm.y, wyA,
                       fmaf(qm.z, wzA, fmaf(qm.w, wrA, biasA))));
            float hB = fmaf(qm.x, wxB, fmaf(qm.y, wyB,
                       fmaf(qm.z, wzB, fmaf(qm.w, wrB, biasB))));
            s_h1[w][m][cA] = fmaxf(hA, 0.0f);
            s_h1[w][m][cB] = fmaxf(hB, 0.0f);
        }

        // Prefetch next pillar (latency hidden under layer 2)
        float4 qn = make_float4(0.f, 0.f, 0.f, 0.f);
        int nn = 0; int2 ccn = make_int2(0, 0);
        if (pn < P) {
            qn  = pillars[(long long)pn * 32 + lane];
            nn  = npts[pn];  nn = nn < 0 ? 0 : (nn > 32 ? 32 : nn);
            ccn = coords[pn];
        }

        __syncwarp();                     // s_h1 visible

        // Layer 2 + running max: 2 points per iteration, independent acc sets
        float mxA = NEGF, mxB = NEGF;
        int m = 0;
        for (; m + 2 <= n; m += 2) {
            const ulonglong2* h0 = (const ulonglong2*)s_h1[w][m];
            const ulonglong2* h1 = (const ulonglong2*)s_h1[w][m + 1];
            unsigned long long a0 = 0ull, a1 = 0ull, a2 = 0ull, a3 = 0ull;
            unsigned long long b0 = 0ull, b1 = 0ull, b2 = 0ull, b3 = 0ull;
#pragma unroll
            for (int t = 0; t < 16; t++) {
                ulonglong2 u = h0[t];     // (h[4t],h[4t+1]) | (h[4t+2],h[4t+3])
                ulonglong2 v = h1[t];
                FMA2(a0, u.x, wA[2 * t]);
                FMA2(a1, u.y, wA[2 * t + 1]);
                FMA2(a2, u.x, wB[2 * t]);
                FMA2(a3, u.y, wB[2 * t + 1]);
                FMA2(b0, v.x, wA[2 * t]);
                FMA2(b1, v.y, wA[2 * t + 1]);
                FMA2(b2, v.x, wB[2 * t]);
                FMA2(b3, v.y, wB[2 * t + 1]);
            }
            unsigned long long sA0, sB0, sA1, sB1;
            ADD2(sA0, a0, a1);
            ADD2(sB0, a2, a3);
            ADD2(sA1, b0, b1);
            ADD2(sB1, b2, b3);
            float lo, hi;
            UNPK2(lo, hi, sA0); mxA = fmaxf(mxA, lo + hi);
            UNPK2(lo, hi, sB0); mxB = fmaxf(mxB, lo + hi);
            UNPK2(lo, hi, sA1); mxA = fmaxf(mxA, lo + hi);
            UNPK2(lo, hi, sB1); mxB = fmaxf(mxB, lo + hi);
        }
        if (m < n) {                      // odd tail point
            const ulonglong2* h0 = (const ulonglong2*)s_h1[w][m];
            unsigned long long a0 = 0ull, a1 = 0ull, a2 = 0ull, a3 = 0ull;
#pragma unroll
            for (int t = 0; t < 16; t++) {
                ulonglong2 u = h0[t];
                FMA2(a0, u.x, wA[2 * t]);
                FMA2(a1, u.y, wA[2 * t + 1]);
                FMA2(a2, u.x, wB[2 * t]);
                FMA2(a3, u.y, wB[2 * t + 1]);
            }
            unsigned long long sA0, sB0;
            ADD2(sA0, a0, a1);
            ADD2(sB0, a2, a3);
            float lo, hi;
            UNPK2(lo, hi, sA0); mxA = fmaxf(mxA, lo + hi);
            UNPK2(lo, hi, sB0); mxB = fmaxf(mxB, lo + hi);
        }

        out[(long long)p * 64 + cA] = (n > 0) ? fmaxf(mxA + b2A, 0.0f) : NEGF;
        out[(long long)p * 64 + cB] = (n > 0) ? fmaxf(mxB + b2B, 0.0f) : NEGF;

        q = qn; n = nn; cc = ccn; p = pn;
    }
}

// ---------------------------------------------------------------------------
// kernel_launch
// Inputs: 0 pillars f32 (P,32,4)  1 coords i32 (P,2)  2 npts i32 (P,)
//         3 W1 4 b1 5 g1 6 beta1 7 m1 8 v1  9 W2 10 b2 11 g2 12 beta2 13 m2 14 v2
// Output: f32 (P, 64)
// ---------------------------------------------------------------------------
extern "C" void kernel_launch(void* const* d_in, const int* in_sizes, int n_in,
                              void* d_out, int out_size) {
    const float4* pillars = (const float4*)d_in[0];
    const int2*   coords  = (const int2*)d_in[1];
    const int*    npts    = (const int*)d_in[2];
    const int P = in_sizes[2];

    pfn_prep<<<1, 64>>>((const float*)d_in[3], (const float*)d_in[4],
                        (const float*)d_in[5], (const float*)d_in[6],
                        (const float*)d_in[7], (const float*)d_in[8],
                        (const float*)d_in[9], (const float*)d_in[10],
                        (const float*)d_in[11], (const float*)d_in[12],
                        (const float*)d_in[13], (const float*)d_in[14]);

    int grid = 2368;                       // 2 pillar streams per CTA
    if (grid * 2 > P) grid = (P + 1) / 2;
    pfn_main<<<grid, 64>>>(pillars, coords, npts, (float*)d_out, P);
}